// round 16
// baseline (speedup 1.0000x reference)
#include <cuda_runtime.h>
#include <cuda_bf16.h>
#include <cuda_fp16.h>
#include <math.h>

// ---------------- problem constants ----------------
constexpr int CB   = 2;
constexpr int CT   = 2048;
constexpr int CD   = 1024;
constexpr int CNH  = 16;
constexpr int CNKV = 4;
constexpr int CHD  = 64;
constexpr int CGROUPS = CNH / CNKV;       // 4
constexpr int CNQKV = (CNH + 2*CNKV)*CHD; // 1536
constexpr int CM = CB * CT;               // 4096
constexpr int CD2 = CD/2;                 // 512 u32 per row

// ---------------- scratch: packed bf16x2 hi/lo planes ----------------
__device__ unsigned g_xhi[(size_t)CM*CD2],  g_xlo[(size_t)CM*CD2];
__device__ unsigned g_wqhi[(size_t)CNQKV*CD2], g_wqlo[(size_t)CNQKV*CD2];
__device__ unsigned g_wohi[(size_t)CD*CD2], g_wolo[(size_t)CD*CD2];
__device__ unsigned g_aohi[(size_t)CM*CD2], g_aolo[(size_t)CM*CD2];
__device__ unsigned g_qhi[(size_t)CB*CNH*CT*32], g_qlo[(size_t)CB*CNH*CT*32];
__device__ unsigned g_khi[(size_t)CB*CNKV*CT*32], g_klo[(size_t)CB*CNKV*CT*32];
__device__ unsigned g_vh [(size_t)CB*CNKV*CT*32];          // fp16x2
__device__ float    g_v  [(size_t)CB*CNKV*CT*CHD];         // f32 (epilogue)

// ---------------- helpers ----------------
__device__ __forceinline__ unsigned sptr(const void* p) {
    return (unsigned)__cvta_generic_to_shared(p);
}
__device__ __forceinline__ void cpa(unsigned saddr, const void* g) {
    asm volatile("cp.async.ca.shared.global [%0], [%1], 16;" :: "r"(saddr), "l"(g));
}
__device__ __forceinline__ void cpcommit() { asm volatile("cp.async.commit_group;"); }
__device__ __forceinline__ void cpwait0()  { asm volatile("cp.async.wait_group 0;"); }
__device__ __forceinline__ void ldsm4(unsigned& r0, unsigned& r1, unsigned& r2, unsigned& r3,
                                      unsigned addr) {
    asm volatile("ldmatrix.sync.aligned.m8n8.x4.shared.b16 {%0,%1,%2,%3}, [%4];"
                 : "=r"(r0), "=r"(r1), "=r"(r2), "=r"(r3) : "r"(addr));
}
__device__ __forceinline__ void ldsm4t(unsigned& r0, unsigned& r1, unsigned& r2, unsigned& r3,
                                       unsigned addr) {
    asm volatile("ldmatrix.sync.aligned.m8n8.x4.trans.shared.b16 {%0,%1,%2,%3}, [%4];"
                 : "=r"(r0), "=r"(r1), "=r"(r2), "=r"(r3) : "r"(addr));
}
__device__ __forceinline__ void mma16(float* c, const unsigned* a, const unsigned* b) {
    asm volatile(
        "mma.sync.aligned.m16n8k16.row.col.f32.bf16.bf16.f32 "
        "{%0,%1,%2,%3},{%4,%5,%6,%7},{%8,%9},{%0,%1,%2,%3};"
        : "+f"(c[0]), "+f"(c[1]), "+f"(c[2]), "+f"(c[3])
        : "r"(a[0]), "r"(a[1]), "r"(a[2]), "r"(a[3]), "r"(b[0]), "r"(b[1]));
}
__device__ __forceinline__ void mmah(float* c, const unsigned* a, const unsigned* b) {
    asm volatile(
        "mma.sync.aligned.m16n8k16.row.col.f32.f16.f16.f32 "
        "{%0,%1,%2,%3},{%4,%5,%6,%7},{%8,%9},{%0,%1,%2,%3};"
        : "+f"(c[0]), "+f"(c[1]), "+f"(c[2]), "+f"(c[3])
        : "r"(a[0]), "r"(a[1]), "r"(a[2]), "r"(a[3]), "r"(b[0]), "r"(b[1]));
}
__device__ __forceinline__ void split2(float x, float y, unsigned& hi, unsigned& lo) {
    __nv_bfloat16 hx = __float2bfloat16(x);
    __nv_bfloat16 hy = __float2bfloat16(y);
    __nv_bfloat16 lx = __float2bfloat16(x - __bfloat162float(hx));
    __nv_bfloat16 ly = __float2bfloat16(y - __bfloat162float(hy));
    hi = (unsigned)__bfloat16_as_ushort(hx) | ((unsigned)__bfloat16_as_ushort(hy) << 16);
    lo = (unsigned)__bfloat16_as_ushort(lx) | ((unsigned)__bfloat16_as_ushort(ly) << 16);
}

// =================================================================
// Prep: split x, w_qkv, w_out into bf16 hi/lo planes. 1 row per block.
// =================================================================
__global__ void split_rows(const float* __restrict__ x,
                           const float* __restrict__ wq,
                           const float* __restrict__ wo) {
    int r = blockIdx.x;
    const float* src; unsigned *hi, *lo;
    if (r < CM)                 { src = x  + (size_t)r*CD;            hi = g_xhi  + (size_t)r*CD2;            lo = g_xlo  + (size_t)r*CD2; }
    else if (r < CM + CNQKV)    { int rr = r - CM;       src = wq + (size_t)rr*CD; hi = g_wqhi + (size_t)rr*CD2; lo = g_wqlo + (size_t)rr*CD2; }
    else                        { int rr = r - CM - CNQKV; src = wo + (size_t)rr*CD; hi = g_wohi + (size_t)rr*CD2; lo = g_wolo + (size_t)rr*CD2; }
    int c = threadIdx.x;   // 0..255, one float4 each
    float4 v = ((const float4*)src)[c];
    unsigned h0, l0, h1, l1;
    split2(v.x, v.y, h0, l0);
    split2(v.z, v.w, h1, l1);
    hi[2*c] = h0; hi[2*c+1] = h1;
    lo[2*c] = l0; lo[2*c+1] = l1;
}

// =================================================================
// Dense GEMM: pre-split planes + cp.async double buffer + ldmatrix.
// R16: 128 threads, 4 warps (2m x 2n), warp tile 64x64 — fragment
// reuse up (85 B smem per MMA vs 128, under the 128 B/cyc crossbar).
// CTA tile 128x128, K-chunk 32 floats; padded stride-20 smem;
// mainloop = proven R14 pattern (cpwait0; sync; issue next; compute).
// =================================================================
__device__ __forceinline__ void scat2(int m, int n, float v0, float v1,
                                      const float* qsc, const float* ksc) {
    int b = m >> 11, t = m & (CT - 1);
    if (n < CNH*CHD) {
        int hh = n >> 6, d = n & 63;
        float s = qsc[hh] * 0.125f;         // fold softmax scale
        unsigned hi, lo; split2(v0*s, v1*s, hi, lo);
        size_t idx = (((size_t)b*CNH + hh)*CT + t)*32 + (d >> 1);
        g_qhi[idx] = hi; g_qlo[idx] = lo;
    } else if (n < (CNH + CNKV)*CHD) {
        int n2 = n - CNH*CHD; int hh = n2 >> 6, d = n2 & 63;
        float s = ksc[hh];
        unsigned hi, lo; split2(v0*s, v1*s, hi, lo);
        size_t idx = (((size_t)b*CNKV + hh)*CT + t)*32 + (d >> 1);
        g_khi[idx] = hi; g_klo[idx] = lo;
    } else {
        int n2 = n - (CNH + CNKV)*CHD; int hh = n2 >> 6, d = n2 & 63;
        size_t base = (((size_t)b*CNKV + hh)*CT + t)*CHD + d;
        *(float2*)&g_v[base] = make_float2(v0, v1);
        __half2 hp = __floats2half2_rn(v0, v1);
        g_vh[base >> 1] = *(unsigned*)&hp;
    }
}

template<int EPI>
__global__ __launch_bounds__(128, 2) void gemm_pl(const float* __restrict__ qsc,
                                                  const float* __restrict__ ksc,
                                                  const float* __restrict__ cs,
                                                  const float* __restrict__ sn,
                                                  float* __restrict__ out) {
    extern __shared__ unsigned sh[];
    const int tid = threadIdx.x, lane = tid & 31, warp = tid >> 5;
    const int wm = warp >> 1, wn = warp & 1;
    const int g = lane >> 2, t4 = lane & 3;
    const int bm = blockIdx.y, bn = blockIdx.x;

    const unsigned* Ahi_g = EPI ? g_xhi  : g_aohi;
    const unsigned* Alo_g = EPI ? g_xlo  : g_aolo;
    const unsigned* Bhi_g = EPI ? g_wqhi : g_wohi;
    const unsigned* Blo_g = EPI ? g_wqlo : g_wolo;

    // cp.async: 128 rows x 4 chunks (16 u32) per plane; 4 chunks/thread/plane.
    int rr_[4], cc_[4]; unsigned so_[4];
#pragma unroll
    for (int i = 0; i < 4; i++) {
        int id = tid + 128*i;
        rr_[i] = id >> 2; cc_[i] = (id & 3) << 2;
        so_[i] = (unsigned)(rr_[i]*20 + cc_[i]) * 4;
    }
    const unsigned sbase = sptr(sh);

    // ldmatrix lane addressing (stride 40 halves = 80 B)
    const int aRow = lane & 15, aK = (lane >> 4) << 3;
    const int bRow = ((lane >> 4) << 3) + (lane & 7), bK = lane & 8;
    unsigned aO[4], bO[4];
#pragma unroll
    for (int mt = 0; mt < 4; mt++) aO[mt] = ((unsigned)(wm*64 + mt*16 + aRow)*40 + aK) * 2;
#pragma unroll
    for (int p = 0; p < 4; p++)   bO[p]  = ((unsigned)(wn*64 + p*16 + bRow)*40 + bK) * 2;

    float acc[4][8][4];
#pragma unroll
    for (int mt = 0; mt < 4; mt++)
#pragma unroll
        for (int nt = 0; nt < 8; nt++)
#pragma unroll
            for (int c = 0; c < 4; c++) acc[mt][nt][c] = 0.f;

    auto issue = [&](int s, int kt) {
        unsigned sb = sbase + (unsigned)s*40960u;
        int k2 = kt >> 1;
#pragma unroll
        for (int i = 0; i < 4; i++) {
            size_t a = (size_t)(bm*128 + rr_[i])*CD2 + k2 + cc_[i];
            size_t b = (size_t)(bn*128 + rr_[i])*CD2 + k2 + cc_[i];
            cpa(sb         + so_[i], Ahi_g + a);
            cpa(sb + 10240 + so_[i], Alo_g + a);
            cpa(sb + 20480 + so_[i], Bhi_g + b);
            cpa(sb + 30720 + so_[i], Blo_g + b);
        }
        cpcommit();
    };

    issue(0, 0);
    int s = 0;
    for (int kt = 0; kt < CD; kt += 32) {
        cpwait0();
        __syncthreads();
        if (kt + 32 < CD) issue(s ^ 1, kt + 32);
        unsigned base = sbase + (unsigned)s*40960u;
#pragma unroll
        for (int ks = 0; ks < 2; ks++) {
            unsigned bh[8][2], bl[8][2];
#pragma unroll
            for (int p = 0; p < 4; p++) {
                ldsm4(bh[2*p][0], bh[2*p][1], bh[2*p+1][0], bh[2*p+1][1], base + 20480 + bO[p] + ks*32);
                ldsm4(bl[2*p][0], bl[2*p][1], bl[2*p+1][0], bl[2*p+1][1], base + 30720 + bO[p] + ks*32);
            }
#pragma unroll
            for (int mt = 0; mt < 4; mt++) {
                unsigned ah[4], al[4];
                ldsm4(ah[0], ah[1], ah[2], ah[3], base         + aO[mt] + ks*32);
                ldsm4(al[0], al[1], al[2], al[3], base + 10240 + aO[mt] + ks*32);
#pragma unroll
                for (int nt = 0; nt < 8; nt++) mma16(acc[mt][nt], ah, bh[nt]);
#pragma unroll
                for (int nt = 0; nt < 8; nt++) mma16(acc[mt][nt], ah, bl[nt]);
#pragma unroll
                for (int nt = 0; nt < 8; nt++) mma16(acc[mt][nt], al, bh[nt]);
            }
        }
        s ^= 1;
    }

    // ---------------- epilogue ----------------
    const int n_base = bn*128 + wn*64;           // warp spans exactly one head
    const bool ropew = (EPI == 1) && (n_base < (CNH + CNKV)*CHD);
#pragma unroll
    for (int mt = 0; mt < 4; mt++) {
        int m0 = bm*128 + wm*64 + mt*16 + g;
        if (ropew) {
            int ta = m0 & (CT - 1);
#pragma unroll
            for (int c = 0; c < 4; c++) {
                int i = 2*t4 + (c & 1);
                int t = ta + ((c < 2) ? 0 : 8);
                float cc = cs[t*8 + i], ss = sn[t*8 + i];
                float x1 = acc[mt][0][c], x2 = acc[mt][1][c];
                acc[mt][0][c] = x1*cc - x2*ss;
                acc[mt][1][c] = x1*ss + x2*cc;
            }
        }
#pragma unroll
        for (int nt = 0; nt < 8; nt++) {
            int n0 = n_base + nt*8 + 2*t4;
            if (EPI == 0) {
                *(float2*)(out + (size_t)m0*CD + n0)     = make_float2(acc[mt][nt][0], acc[mt][nt][1]);
                *(float2*)(out + (size_t)(m0+8)*CD + n0) = make_float2(acc[mt][nt][2], acc[mt][nt][3]);
            } else {
                scat2(m0,   n0, acc[mt][nt][0], acc[mt][nt][1], qsc, ksc);
                scat2(m0+8, n0, acc[mt][nt][2], acc[mt][nt][3], qsc, ksc);
            }
        }
    }
}

// =================================================================
// Flash attention (exact R14): pre-split Q/K planes, fp16 V; cp.async
// K/V pipeline. Q tile 128, K tile 64, 8 warps, 2 stages.
// P never touches smem — S accumulator frags ARE the fp16 A frags.
// smem (u32): Qhi 4608 | Qlo 4608 | 2 x (Khi 2304, Klo 2304, Vh 2304)
// =================================================================
__global__ __launch_bounds__(256, 2) void attn_pl() {
    extern __shared__ unsigned sm[];
    const int tid = threadIdx.x, lane = tid & 31, warp = tid >> 5;
    const int g = lane >> 2, t4 = lane & 3;
    const int qb = (int)gridDim.x - 1 - (int)blockIdx.x;
    const int h = blockIdx.y, b = blockIdx.z;
    const int kvh = h / CGROUPS;
    const int w16 = warp * 16;
    const int qrow = qb*128 + w16;

    const unsigned* qhg = g_qhi + (((size_t)b*CNH + h)*CT + (size_t)qb*128)*32;
    const unsigned* qlg = g_qlo + (((size_t)b*CNH + h)*CT + (size_t)qb*128)*32;
    const unsigned* khg = g_khi + ((size_t)b*CNKV + kvh)*CT*32;
    const unsigned* klg = g_klo + ((size_t)b*CNKV + kvh)*CT*32;
    const unsigned* vhg = g_vh  + ((size_t)b*CNKV + kvh)*CT*32;
    const float*    vbase = g_v + ((size_t)b*CNKV + kvh)*CT*CHD;

    const unsigned sbase = sptr(sm);

    // --- load Q tile (both planes): 128 rows x 8 chunks ---
#pragma unroll
    for (int i = 0; i < 4; i++) {
        int idx = tid + 256*i, row = idx >> 3, cc = (idx & 7) << 2;
        *(uint4*)&sm[row*36 + cc]        = *(const uint4*)(qhg + (size_t)row*32 + cc);
        *(uint4*)&sm[4608 + row*36 + cc] = *(const uint4*)(qlg + (size_t)row*32 + cc);
    }

    // cp.async chunk assignment for K/V: 64 rows x 8 chunks (32 u32) per plane
    const int kr0 = tid >> 3,       kc0 = (tid & 7) << 2;
    const int kr1 = (tid+256) >> 3, kc1 = (tid & 7) << 2;
    const unsigned ko0 = (kr0*36 + kc0)*4, ko1 = (kr1*36 + kc1)*4;

    auto issueKV = [&](int s, int krow) {
        unsigned sb = sbase + (9216 + s*6912)*4;
        size_t g0 = (size_t)(krow + kr0)*32 + kc0;
        size_t g1 = (size_t)(krow + kr1)*32 + kc1;
        cpa(sb +        ko0, khg + g0);
        cpa(sb +        ko1, khg + g1);
        cpa(sb + 9216 + ko0, klg + g0);
        cpa(sb + 9216 + ko1, klg + g1);
        cpa(sb + 18432 + ko0, vhg + g0);
        cpa(sb + 18432 + ko1, vhg + g1);
        cpcommit();
    };

    // ldmatrix lane addressing (stride 72 halves = 144 B)
    const int aRow = lane & 15, aK = (lane >> 4) << 3;
    const int bRow = ((lane >> 4) << 3) + (lane & 7), bK = lane & 8;
    const unsigned qHiA = sbase + ((unsigned)(w16 + aRow)*72 + aK)*2;
    const unsigned qLoA = qHiA + 4608*4;
    unsigned kO[4];
#pragma unroll
    for (int p = 0; p < 4; p++) kO[p] = ((unsigned)(p*16 + bRow)*72 + bK)*2;
    unsigned vO[4];
#pragma unroll
    for (int p = 0; p < 4; p++)
        vO[p] = (((unsigned)((lane & 8) + (lane & 7)))*72 + p*16 + ((lane >> 4) << 3))*2;

    float mst[2] = {-1e30f, -1e30f}, lst[2] = {0.f, 0.f};
    float o[8][4];
#pragma unroll
    for (int dt = 0; dt < 8; dt++)
#pragma unroll
        for (int c = 0; c < 4; c++) o[dt][c] = 0.f;

    const int jbmax = 2*qb + 1;
    issueKV(0, 0);
    int st = 0;
    for (int jb = 0; jb <= jbmax; jb++) {
        const int krow = jb*64;
        cpwait0();
        __syncthreads();
        if (jb < jbmax) issueKV(st ^ 1, krow + 64);

        if (krow <= qrow + 15) {
            const unsigned kb   = sbase + (9216 + st*6912)*4;
            const unsigned kbLo = kb + 9216;
            const unsigned vb0  = kb + 18432;

            // S = Q K^T, bf16x2: hh + hl + lh
            float s[8][4];
#pragma unroll
            for (int nt = 0; nt < 8; nt++)
#pragma unroll
                for (int c = 0; c < 4; c++) s[nt][c] = 0.f;
#pragma unroll
            for (int ks = 0; ks < 4; ks++) {
                unsigned ah[4], al[4];
                ldsm4(ah[0], ah[1], ah[2], ah[3], qHiA + ks*32);
                ldsm4(al[0], al[1], al[2], al[3], qLoA + ks*32);
#pragma unroll
                for (int p = 0; p < 4; p++) {
                    unsigned bh[4], bl[4];
                    ldsm4(bh[0], bh[1], bh[2], bh[3], kb   + kO[p] + ks*32);
                    ldsm4(bl[0], bl[1], bl[2], bl[3], kbLo + kO[p] + ks*32);
                    mma16(s[2*p],   ah, &bh[0]);
                    mma16(s[2*p],   ah, &bl[0]);
                    mma16(s[2*p],   al, &bh[0]);
                    mma16(s[2*p+1], ah, &bh[2]);
                    mma16(s[2*p+1], ah, &bl[2]);
                    mma16(s[2*p+1], al, &bh[2]);
                }
            }

            if (krow + 63 > qrow) {   // causal mask
                int q0 = qrow + g, q1 = q0 + 8;
#pragma unroll
                for (int nt = 0; nt < 8; nt++) {
                    int kc = krow + nt*8 + 2*t4;
                    if (kc     > q0) s[nt][0] = -1e30f;
                    if (kc + 1 > q0) s[nt][1] = -1e30f;
                    if (kc     > q1) s[nt][2] = -1e30f;
                    if (kc + 1 > q1) s[nt][3] = -1e30f;
                }
            }

            // online softmax
            float mx0 = -1e30f, mx1 = -1e30f;
#pragma unroll
            for (int nt = 0; nt < 8; nt++) {
                mx0 = fmaxf(mx0, fmaxf(s[nt][0], s[nt][1]));
                mx1 = fmaxf(mx1, fmaxf(s[nt][2], s[nt][3]));
            }
            mx0 = fmaxf(mx0, __shfl_xor_sync(0xffffffffu, mx0, 1));
            mx0 = fmaxf(mx0, __shfl_xor_sync(0xffffffffu, mx0, 2));
            mx1 = fmaxf(mx1, __shfl_xor_sync(0xffffffffu, mx1, 1));
            mx1 = fmaxf(mx1, __shfl_xor_sync(0xffffffffu, mx1, 2));
            float mn0 = fmaxf(mst[0], mx0), mn1 = fmaxf(mst[1], mx1);
            float al0 = __expf(mst[0] - mn0), al1 = __expf(mst[1] - mn1);
            mst[0] = mn0; mst[1] = mn1;
            float rs0 = 0.f, rs1 = 0.f;
#pragma unroll
            for (int nt = 0; nt < 8; nt++) {
                s[nt][0] = __expf(s[nt][0] - mn0); rs0 += s[nt][0];
                s[nt][1] = __expf(s[nt][1] - mn0); rs0 += s[nt][1];
                s[nt][2] = __expf(s[nt][2] - mn1); rs1 += s[nt][2];
                s[nt][3] = __expf(s[nt][3] - mn1); rs1 += s[nt][3];
            }
            rs0 += __shfl_xor_sync(0xffffffffu, rs0, 1);
            rs0 += __shfl_xor_sync(0xffffffffu, rs0, 2);
            rs1 += __shfl_xor_sync(0xffffffffu, rs1, 1);
            rs1 += __shfl_xor_sync(0xffffffffu, rs1, 2);
            lst[0] = lst[0]*al0 + rs0;
            lst[1] = lst[1]*al1 + rs1;
#pragma unroll
            for (int dt = 0; dt < 8; dt++) {
                o[dt][0] *= al0; o[dt][1] *= al0;
                o[dt][2] *= al1; o[dt][3] *= al1;
            }

            // O += P V  — P fragments built directly from S registers
#pragma unroll
            for (int ks = 0; ks < 4; ks++) {
                unsigned pa[4];
                __half2 hp;
                hp = __floats2half2_rn(s[2*ks][0],   s[2*ks][1]);   pa[0] = *(unsigned*)&hp;
                hp = __floats2half2_rn(s[2*ks][2],   s[2*ks][3]);   pa[1] = *(unsigned*)&hp;
                hp = __floats2half2_rn(s[2*ks+1][0], s[2*ks+1][1]); pa[2] = *(unsigned*)&hp;
                hp = __floats2half2_rn(s[2*ks+1][2], s[2*ks+1][3]); pa[3] = *(unsigned*)&hp;
#pragma unroll
                for (int p = 0; p < 4; p++) {
                    unsigned vv[4];
                    ldsm4t(vv[0], vv[1], vv[2], vv[3], vb0 + vO[p] + ks*2304);
                    mmah(o[2*p],   pa, &vv[0]);
                    mmah(o[2*p+1], pa, &vv[2]);
                }
            }
        }
        st ^= 1;
    }

    // epilogue: normalize + subtract projection onto v[t]; write bf16 planes
#pragma unroll
    for (int rr = 0; rr < 2; rr++) {
        int t = qrow + g + rr*8;
        float inv = 1.f / lst[rr];
        float ov[8][2];
        float pd = 0.f, pn = 0.f;
#pragma unroll
        for (int dt = 0; dt < 8; dt++) {
            float2 vv = *(const float2*)(vbase + (size_t)t*CHD + dt*8 + 2*t4);
            float o0 = o[dt][rr*2 + 0]*inv, o1 = o[dt][rr*2 + 1]*inv;
            ov[dt][0] = o0; ov[dt][1] = o1;
            pd += o0*vv.x + o1*vv.y;
            pn += vv.x*vv.x + vv.y*vv.y;
        }
        pd += __shfl_xor_sync(0xffffffffu, pd, 1);
        pd += __shfl_xor_sync(0xffffffffu, pd, 2);
        pn += __shfl_xor_sync(0xffffffffu, pn, 1);
        pn += __shfl_xor_sync(0xffffffffu, pn, 2);
        float coef = pd / fmaxf(pn, 1e-8f);
        size_t rowbase = ((size_t)b*CT + t)*CD2 + h*32;
#pragma unroll
        for (int dt = 0; dt < 8; dt++) {
            float2 vv = *(const float2*)(vbase + (size_t)t*CHD + dt*8 + 2*t4);
            unsigned hi, lo;
            split2(ov[dt][0] - coef*vv.x, ov[dt][1] - coef*vv.y, hi, lo);
            int d2 = dt*4 + t4;
            g_aohi[rowbase + d2] = hi;
            g_aolo[rowbase + d2] = lo;
        }
    }
}

// =================================================================
extern "C" void kernel_launch(void* const* d_in, const int* in_sizes, int n_in,
                              void* d_out, int out_size) {
    (void)in_sizes; (void)n_in; (void)out_size;
    const float* x    = (const float*)d_in[0];
    const float* cs   = (const float*)d_in[1];
    const float* sn   = (const float*)d_in[2];
    const float* wqkv = (const float*)d_in[4];
    const float* wout = (const float*)d_in[5];
    const float* qsc  = (const float*)d_in[6];
    const float* ksc  = (const float*)d_in[7];
    float* out = (float*)d_out;

    split_rows<<<CM + CNQKV + CD, 256>>>(x, wqkv, wout);

    const int gemm_smem = 2 * 40960;     // 81920 B
    cudaFuncSetAttribute(gemm_pl<1>, cudaFuncAttributeMaxDynamicSharedMemorySize, gemm_smem);
    cudaFuncSetAttribute(gemm_pl<0>, cudaFuncAttributeMaxDynamicSharedMemorySize, gemm_smem);

    dim3 g1(CNQKV/128, CM/128);          // 12 x 32
    gemm_pl<1><<<g1, 128, gemm_smem>>>(qsc, ksc, cs, sn, nullptr);

    const int attn_smem = (9216 + 2*6912) * 4;   // 92160 B
    cudaFuncSetAttribute(attn_pl, cudaFuncAttributeMaxDynamicSharedMemorySize, attn_smem);
    dim3 g2(CT/128, CNH, CB);            // 16 x 16 x 2
    attn_pl<<<g2, 256, attn_smem>>>();

    dim3 g3(CD/128, CM/128);             // 8 x 32
    gemm_pl<0><<<g3, 128, gemm_smem>>>(nullptr, nullptr, nullptr, nullptr, out);
}

// round 17
// speedup vs baseline: 1.7156x; 1.7156x over previous
#include <cuda_runtime.h>
#include <cuda_bf16.h>
#include <cuda_fp16.h>
#include <math.h>

// ---------------- problem constants ----------------
constexpr int CB   = 2;
constexpr int CT   = 2048;
constexpr int CD   = 1024;
constexpr int CNH  = 16;
constexpr int CNKV = 4;
constexpr int CHD  = 64;
constexpr int CGROUPS = CNH / CNKV;       // 4
constexpr int CNQKV = (CNH + 2*CNKV)*CHD; // 1536
constexpr int CM = CB * CT;               // 4096
constexpr int CD2 = CD/2;                 // 512 u32 per row

// ---------------- scratch: packed bf16x2 hi/lo planes ----------------
__device__ unsigned g_xhi[(size_t)CM*CD2],  g_xlo[(size_t)CM*CD2];
__device__ unsigned g_wqhi[(size_t)CNQKV*CD2], g_wqlo[(size_t)CNQKV*CD2];
__device__ unsigned g_wohi[(size_t)CD*CD2], g_wolo[(size_t)CD*CD2];
__device__ unsigned g_aohi[(size_t)CM*CD2], g_aolo[(size_t)CM*CD2];
__device__ unsigned g_qhi[(size_t)CB*CNH*CT*32], g_qlo[(size_t)CB*CNH*CT*32];
__device__ unsigned g_khi[(size_t)CB*CNKV*CT*32], g_klo[(size_t)CB*CNKV*CT*32];
__device__ unsigned g_vh [(size_t)CB*CNKV*CT*32];          // fp16x2
__device__ float    g_v  [(size_t)CB*CNKV*CT*CHD];         // f32 (epilogue)

// ---------------- helpers ----------------
__device__ __forceinline__ unsigned sptr(const void* p) {
    return (unsigned)__cvta_generic_to_shared(p);
}
__device__ __forceinline__ void cpa(unsigned saddr, const void* g) {
    asm volatile("cp.async.ca.shared.global [%0], [%1], 16;" :: "r"(saddr), "l"(g));
}
__device__ __forceinline__ void cpcommit() { asm volatile("cp.async.commit_group;"); }
__device__ __forceinline__ void cpwait0()  { asm volatile("cp.async.wait_group 0;"); }
__device__ __forceinline__ void ldsm4(unsigned& r0, unsigned& r1, unsigned& r2, unsigned& r3,
                                      unsigned addr) {
    asm volatile("ldmatrix.sync.aligned.m8n8.x4.shared.b16 {%0,%1,%2,%3}, [%4];"
                 : "=r"(r0), "=r"(r1), "=r"(r2), "=r"(r3) : "r"(addr));
}
__device__ __forceinline__ void ldsm4t(unsigned& r0, unsigned& r1, unsigned& r2, unsigned& r3,
                                       unsigned addr) {
    asm volatile("ldmatrix.sync.aligned.m8n8.x4.trans.shared.b16 {%0,%1,%2,%3}, [%4];"
                 : "=r"(r0), "=r"(r1), "=r"(r2), "=r"(r3) : "r"(addr));
}
__device__ __forceinline__ void mma16(float* c, const unsigned* a, const unsigned* b) {
    asm volatile(
        "mma.sync.aligned.m16n8k16.row.col.f32.bf16.bf16.f32 "
        "{%0,%1,%2,%3},{%4,%5,%6,%7},{%8,%9},{%0,%1,%2,%3};"
        : "+f"(c[0]), "+f"(c[1]), "+f"(c[2]), "+f"(c[3])
        : "r"(a[0]), "r"(a[1]), "r"(a[2]), "r"(a[3]), "r"(b[0]), "r"(b[1]));
}
__device__ __forceinline__ void mmah(float* c, const unsigned* a, const unsigned* b) {
    asm volatile(
        "mma.sync.aligned.m16n8k16.row.col.f32.f16.f16.f32 "
        "{%0,%1,%2,%3},{%4,%5,%6,%7},{%8,%9},{%0,%1,%2,%3};"
        : "+f"(c[0]), "+f"(c[1]), "+f"(c[2]), "+f"(c[3])
        : "r"(a[0]), "r"(a[1]), "r"(a[2]), "r"(a[3]), "r"(b[0]), "r"(b[1]));
}
__device__ __forceinline__ void split2(float x, float y, unsigned& hi, unsigned& lo) {
    __nv_bfloat16 hx = __float2bfloat16(x);
    __nv_bfloat16 hy = __float2bfloat16(y);
    __nv_bfloat16 lx = __float2bfloat16(x - __bfloat162float(hx));
    __nv_bfloat16 ly = __float2bfloat16(y - __bfloat162float(hy));
    hi = (unsigned)__bfloat16_as_ushort(hx) | ((unsigned)__bfloat16_as_ushort(hy) << 16);
    lo = (unsigned)__bfloat16_as_ushort(lx) | ((unsigned)__bfloat16_as_ushort(ly) << 16);
}

// =================================================================
// Prep: split x, w_qkv, w_out into bf16 hi/lo planes. 1 row per block.
// =================================================================
__global__ void split_rows(const float* __restrict__ x,
                           const float* __restrict__ wq,
                           const float* __restrict__ wo) {
    int r = blockIdx.x;
    const float* src; unsigned *hi, *lo;
    if (r < CM)                 { src = x  + (size_t)r*CD;            hi = g_xhi  + (size_t)r*CD2;            lo = g_xlo  + (size_t)r*CD2; }
    else if (r < CM + CNQKV)    { int rr = r - CM;       src = wq + (size_t)rr*CD; hi = g_wqhi + (size_t)rr*CD2; lo = g_wqlo + (size_t)rr*CD2; }
    else                        { int rr = r - CM - CNQKV; src = wo + (size_t)rr*CD; hi = g_wohi + (size_t)rr*CD2; lo = g_wolo + (size_t)rr*CD2; }
    int c = threadIdx.x;   // 0..255, one float4 each
    float4 v = ((const float4*)src)[c];
    unsigned h0, l0, h1, l1;
    split2(v.x, v.y, h0, l0);
    split2(v.z, v.w, h1, l1);
    hi[2*c] = h0; hi[2*c+1] = h1;
    lo[2*c] = l0; lo[2*c+1] = l1;
}

// =================================================================
// QKV GEMM (exact R14): 256 thr, 8 warps (2m x 4n), tile 128x128,
// K-chunk 32 floats, padded stride-20 smem, 2-stage cp.async.
// =================================================================
__device__ __forceinline__ void scat2(int m, int n, float v0, float v1,
                                      const float* qsc, const float* ksc) {
    int b = m >> 11, t = m & (CT - 1);
    if (n < CNH*CHD) {
        int hh = n >> 6, d = n & 63;
        float s = qsc[hh] * 0.125f;         // fold softmax scale
        unsigned hi, lo; split2(v0*s, v1*s, hi, lo);
        size_t idx = (((size_t)b*CNH + hh)*CT + t)*32 + (d >> 1);
        g_qhi[idx] = hi; g_qlo[idx] = lo;
    } else if (n < (CNH + CNKV)*CHD) {
        int n2 = n - CNH*CHD; int hh = n2 >> 6, d = n2 & 63;
        float s = ksc[hh];
        unsigned hi, lo; split2(v0*s, v1*s, hi, lo);
        size_t idx = (((size_t)b*CNKV + hh)*CT + t)*32 + (d >> 1);
        g_khi[idx] = hi; g_klo[idx] = lo;
    } else {
        int n2 = n - (CNH + CNKV)*CHD; int hh = n2 >> 6, d = n2 & 63;
        size_t base = (((size_t)b*CNKV + hh)*CT + t)*CHD + d;
        *(float2*)&g_v[base] = make_float2(v0, v1);
        __half2 hp = __floats2half2_rn(v0, v1);
        g_vh[base >> 1] = *(unsigned*)&hp;
    }
}

__global__ __launch_bounds__(256, 2) void gemm_qkv(const float* __restrict__ qsc,
                                                   const float* __restrict__ ksc,
                                                   const float* __restrict__ cs,
                                                   const float* __restrict__ sn) {
    extern __shared__ unsigned sh[];
    const int tid = threadIdx.x, lane = tid & 31, warp = tid >> 5;
    const int wm = warp >> 2, wn = warp & 3;
    const int g = lane >> 2, t4 = lane & 3;
    const int bm = blockIdx.y, bn = blockIdx.x;

    const int r0 = tid >> 2,        c0 = (tid & 3) << 2;
    const int r1 = (tid + 256) >> 2, c1 = (tid & 3) << 2;
    const unsigned sbase = sptr(sh);
    const unsigned so0 = (r0*20 + c0) * 4, so1 = (r1*20 + c1) * 4;

    const int aRow = lane & 15, aK = (lane >> 4) << 3;
    const int bRow = ((lane >> 4) << 3) + (lane & 7), bK = lane & 8;
    unsigned aO[4], bO[2];
#pragma unroll
    for (int mt = 0; mt < 4; mt++) aO[mt] = ((unsigned)(wm*64 + mt*16 + aRow)*40 + aK) * 2;
#pragma unroll
    for (int p = 0; p < 2; p++)   bO[p]  = ((unsigned)(wn*32 + p*16 + bRow)*40 + bK) * 2;

    float acc[4][4][4];
#pragma unroll
    for (int mt = 0; mt < 4; mt++)
#pragma unroll
        for (int nt = 0; nt < 4; nt++)
#pragma unroll
            for (int c = 0; c < 4; c++) acc[mt][nt][c] = 0.f;

    auto issue = [&](int s, int kt) {
        unsigned sb = sbase + s*40960;
        int k2 = kt >> 1;
        size_t a0 = (size_t)(bm*128 + r0)*CD2 + k2 + c0;
        size_t a1 = (size_t)(bm*128 + r1)*CD2 + k2 + c1;
        size_t b0 = (size_t)(bn*128 + r0)*CD2 + k2 + c0;
        size_t b1 = (size_t)(bn*128 + r1)*CD2 + k2 + c1;
        cpa(sb         + so0, g_xhi  + a0);
        cpa(sb         + so1, g_xhi  + a1);
        cpa(sb + 10240 + so0, g_xlo  + a0);
        cpa(sb + 10240 + so1, g_xlo  + a1);
        cpa(sb + 20480 + so0, g_wqhi + b0);
        cpa(sb + 20480 + so1, g_wqhi + b1);
        cpa(sb + 30720 + so0, g_wqlo + b0);
        cpa(sb + 30720 + so1, g_wqlo + b1);
        cpcommit();
    };

    issue(0, 0);
    int s = 0;
    for (int kt = 0; kt < CD; kt += 32) {
        cpwait0();
        __syncthreads();
        if (kt + 32 < CD) issue(s ^ 1, kt + 32);
        unsigned base = sbase + s*40960;
#pragma unroll
        for (int ks = 0; ks < 2; ks++) {
            unsigned bh[4][2], bl[4][2];
#pragma unroll
            for (int p = 0; p < 2; p++) {
                ldsm4(bh[2*p][0], bh[2*p][1], bh[2*p+1][0], bh[2*p+1][1], base + 20480 + bO[p] + ks*32);
                ldsm4(bl[2*p][0], bl[2*p][1], bl[2*p+1][0], bl[2*p+1][1], base + 30720 + bO[p] + ks*32);
            }
#pragma unroll
            for (int mt = 0; mt < 4; mt++) {
                unsigned ah[4], al[4];
                ldsm4(ah[0], ah[1], ah[2], ah[3], base         + aO[mt] + ks*32);
                ldsm4(al[0], al[1], al[2], al[3], base + 10240 + aO[mt] + ks*32);
#pragma unroll
                for (int nt = 0; nt < 4; nt++) {
                    mma16(acc[mt][nt], ah, bh[nt]);
                    mma16(acc[mt][nt], ah, bl[nt]);
                    mma16(acc[mt][nt], al, bh[nt]);
                }
            }
        }
        s ^= 1;
    }

    const int n_base = bn*128 + wn*32;
    const bool ropew = ((wn & 1) == 0) && (n_base < (CNH + CNKV)*CHD);
#pragma unroll
    for (int mt = 0; mt < 4; mt++) {
        int m0 = bm*128 + wm*64 + mt*16 + g;
        if (ropew) {
            int ta = m0 & (CT - 1);
#pragma unroll
            for (int c = 0; c < 4; c++) {
                int i = 2*t4 + (c & 1);
                int t = ta + ((c < 2) ? 0 : 8);
                float cc = cs[t*8 + i], ss = sn[t*8 + i];
                float x1 = acc[mt][0][c], x2 = acc[mt][1][c];
                acc[mt][0][c] = x1*cc - x2*ss;
                acc[mt][1][c] = x1*ss + x2*cc;
            }
        }
#pragma unroll
        for (int nt = 0; nt < 4; nt++) {
            int n0 = n_base + nt*8 + 2*t4;
            scat2(m0,   n0, acc[mt][nt][0], acc[mt][nt][1], qsc, ksc);
            scat2(m0+8, n0, acc[mt][nt][2], acc[mt][nt][3], qsc, ksc);
        }
    }
}

// =================================================================
// R17: wide out-proj GEMM. 512 thr, 16 warps (2m x 8n), tile 128x256,
// K-chunk 64 floats (4 k16), stride-36-u32 padded smem, 2-stage.
// Per-warp inner code identical to R14 (warp tile 64x32, acc 64 f32).
// Stage: Ahi 18432 | Alo 18432 | Bhi 36864 | Blo 36864 = 110592 B.
// 128 CTAs = one clean wave; barriers per tile halved (16 vs 32).
// =================================================================
__global__ __launch_bounds__(512, 1) void gemm_out(float* __restrict__ out) {
    extern __shared__ unsigned sh[];
    const int tid = threadIdx.x, lane = tid & 31, warp = tid >> 5;
    const int wm = warp >> 3, wn = warp & 7;
    const int g = lane >> 2, t4 = lane & 3;
    const int bm = blockIdx.y, bn = blockIdx.x;

    const unsigned sbase = sptr(sh);
    constexpr unsigned ST = 110592u;          // stage bytes
    constexpr unsigned ALO = 18432u, BHI = 36864u, BLO = 73728u;

    // cp.async mapping: rows x 8 chunks (16B) per plane.
    // A: 1024 chunks/plane (2 per thread); B: 2048 chunks/plane (4 per thread).
    const int ar0 = tid >> 3,         ac0 = tid & 7;
    const int ar1 = (tid + 512) >> 3, ac1 = tid & 7;
    const unsigned aso0 = (unsigned)(ar0*144 + ac0*16);
    const unsigned aso1 = (unsigned)(ar1*144 + ac1*16);
    int br_[4]; unsigned bso_[4];
#pragma unroll
    for (int i = 0; i < 4; i++) {
        int id = tid + 512*i;
        br_[i] = id >> 3;
        bso_[i] = (unsigned)(br_[i]*144 + (id & 7)*16);
    }

    // ldmatrix lane addressing (stride 72 halves = 144 B)
    const int aRow = lane & 15, aK = (lane >> 4) << 3;
    const int bRow = ((lane >> 4) << 3) + (lane & 7), bK = lane & 8;
    unsigned aO[4], bO[2];
#pragma unroll
    for (int mt = 0; mt < 4; mt++) aO[mt] = ((unsigned)(wm*64 + mt*16 + aRow)*72 + aK) * 2;
#pragma unroll
    for (int p = 0; p < 2; p++)   bO[p]  = ((unsigned)(wn*32 + p*16 + bRow)*72 + bK) * 2;

    float acc[4][4][4];
#pragma unroll
    for (int mt = 0; mt < 4; mt++)
#pragma unroll
        for (int nt = 0; nt < 4; nt++)
#pragma unroll
            for (int c = 0; c < 4; c++) acc[mt][nt][c] = 0.f;

    auto issue = [&](int s, int ck) {
        unsigned sb = sbase + (unsigned)s*ST;
        int k2 = ck*32;                       // chunk = 64 floats = 32 u32
        size_t a0 = (size_t)(bm*128 + ar0)*CD2 + k2 + (tid & 7)*4;
        size_t a1 = (size_t)(bm*128 + ar1)*CD2 + k2 + (tid & 7)*4;
        cpa(sb       + aso0, g_aohi + a0);
        cpa(sb       + aso1, g_aohi + a1);
        cpa(sb + ALO + aso0, g_aolo + a0);
        cpa(sb + ALO + aso1, g_aolo + a1);
#pragma unroll
        for (int i = 0; i < 4; i++) {
            size_t b = (size_t)(bn*256 + br_[i])*CD2 + k2 + (tid & 7)*4;
            cpa(sb + BHI + bso_[i], g_wohi + b);
            cpa(sb + BLO + bso_[i], g_wolo + b);
        }
        cpcommit();
    };

    issue(0, 0);
    int s = 0;
    for (int ck = 0; ck < 16; ck++) {
        cpwait0();
        __syncthreads();
        if (ck + 1 < 16) issue(s ^ 1, ck + 1);
        const unsigned base = sbase + (unsigned)s*ST;
#pragma unroll
        for (int ks = 0; ks < 4; ks++) {
            unsigned bh[4][2], bl[4][2];
#pragma unroll
            for (int p = 0; p < 2; p++) {
                ldsm4(bh[2*p][0], bh[2*p][1], bh[2*p+1][0], bh[2*p+1][1], base + BHI + bO[p] + ks*32);
                ldsm4(bl[2*p][0], bl[2*p][1], bl[2*p+1][0], bl[2*p+1][1], base + BLO + bO[p] + ks*32);
            }
#pragma unroll
            for (int mt = 0; mt < 4; mt++) {
                unsigned ah[4], al[4];
                ldsm4(ah[0], ah[1], ah[2], ah[3], base       + aO[mt] + ks*32);
                ldsm4(al[0], al[1], al[2], al[3], base + ALO + aO[mt] + ks*32);
#pragma unroll
                for (int nt = 0; nt < 4; nt++) {
                    mma16(acc[mt][nt], ah, bh[nt]);
                    mma16(acc[mt][nt], ah, bl[nt]);
                    mma16(acc[mt][nt], al, bh[nt]);
                }
            }
        }
        s ^= 1;
    }

    const int n_base = bn*256 + wn*32;
#pragma unroll
    for (int mt = 0; mt < 4; mt++) {
        int m0 = bm*128 + wm*64 + mt*16 + g;
#pragma unroll
        for (int nt = 0; nt < 4; nt++) {
            int n0 = n_base + nt*8 + 2*t4;
            *(float2*)(out + (size_t)m0*CD + n0)     = make_float2(acc[mt][nt][0], acc[mt][nt][1]);
            *(float2*)(out + (size_t)(m0+8)*CD + n0) = make_float2(acc[mt][nt][2], acc[mt][nt][3]);
        }
    }
}

// =================================================================
// Flash attention (exact R14): pre-split Q/K planes, fp16 V; cp.async
// K/V pipeline. Q tile 128, K tile 64, 8 warps, 2 stages.
// P never touches smem — S accumulator frags ARE the fp16 A frags.
// =================================================================
__global__ __launch_bounds__(256, 2) void attn_pl() {
    extern __shared__ unsigned sm[];
    const int tid = threadIdx.x, lane = tid & 31, warp = tid >> 5;
    const int g = lane >> 2, t4 = lane & 3;
    const int qb = (int)gridDim.x - 1 - (int)blockIdx.x;
    const int h = blockIdx.y, b = blockIdx.z;
    const int kvh = h / CGROUPS;
    const int w16 = warp * 16;
    const int qrow = qb*128 + w16;

    const unsigned* qhg = g_qhi + (((size_t)b*CNH + h)*CT + (size_t)qb*128)*32;
    const unsigned* qlg = g_qlo + (((size_t)b*CNH + h)*CT + (size_t)qb*128)*32;
    const unsigned* khg = g_khi + ((size_t)b*CNKV + kvh)*CT*32;
    const unsigned* klg = g_klo + ((size_t)b*CNKV + kvh)*CT*32;
    const unsigned* vhg = g_vh  + ((size_t)b*CNKV + kvh)*CT*32;
    const float*    vbase = g_v + ((size_t)b*CNKV + kvh)*CT*CHD;

    const unsigned sbase = sptr(sm);

#pragma unroll
    for (int i = 0; i < 4; i++) {
        int idx = tid + 256*i, row = idx >> 3, cc = (idx & 7) << 2;
        *(uint4*)&sm[row*36 + cc]        = *(const uint4*)(qhg + (size_t)row*32 + cc);
        *(uint4*)&sm[4608 + row*36 + cc] = *(const uint4*)(qlg + (size_t)row*32 + cc);
    }

    const int kr0 = tid >> 3,       kc0 = (tid & 7) << 2;
    const int kr1 = (tid+256) >> 3, kc1 = (tid & 7) << 2;
    const unsigned ko0 = (kr0*36 + kc0)*4, ko1 = (kr1*36 + kc1)*4;

    auto issueKV = [&](int s, int krow) {
        unsigned sb = sbase + (9216 + s*6912)*4;
        size_t g0 = (size_t)(krow + kr0)*32 + kc0;
        size_t g1 = (size_t)(krow + kr1)*32 + kc1;
        cpa(sb +        ko0, khg + g0);
        cpa(sb +        ko1, khg + g1);
        cpa(sb + 9216 + ko0, klg + g0);
        cpa(sb + 9216 + ko1, klg + g1);
        cpa(sb + 18432 + ko0, vhg + g0);
        cpa(sb + 18432 + ko1, vhg + g1);
        cpcommit();
    };

    const int aRow = lane & 15, aK = (lane >> 4) << 3;
    const int bRow = ((lane >> 4) << 3) + (lane & 7), bK = lane & 8;
    const unsigned qHiA = sbase + ((unsigned)(w16 + aRow)*72 + aK)*2;
    const unsigned qLoA = qHiA + 4608*4;
    unsigned kO[4];
#pragma unroll
    for (int p = 0; p < 4; p++) kO[p] = ((unsigned)(p*16 + bRow)*72 + bK)*2;
    unsigned vO[4];
#pragma unroll
    for (int p = 0; p < 4; p++)
        vO[p] = (((unsigned)((lane & 8) + (lane & 7)))*72 + p*16 + ((lane >> 4) << 3))*2;

    float mst[2] = {-1e30f, -1e30f}, lst[2] = {0.f, 0.f};
    float o[8][4];
#pragma unroll
    for (int dt = 0; dt < 8; dt++)
#pragma unroll
        for (int c = 0; c < 4; c++) o[dt][c] = 0.f;

    const int jbmax = 2*qb + 1;
    issueKV(0, 0);
    int st = 0;
    for (int jb = 0; jb <= jbmax; jb++) {
        const int krow = jb*64;
        cpwait0();
        __syncthreads();
        if (jb < jbmax) issueKV(st ^ 1, krow + 64);

        if (krow <= qrow + 15) {
            const unsigned kb   = sbase + (9216 + st*6912)*4;
            const unsigned kbLo = kb + 9216;
            const unsigned vb0  = kb + 18432;

            float s[8][4];
#pragma unroll
            for (int nt = 0; nt < 8; nt++)
#pragma unroll
                for (int c = 0; c < 4; c++) s[nt][c] = 0.f;
#pragma unroll
            for (int ks = 0; ks < 4; ks++) {
                unsigned ah[4], al[4];
                ldsm4(ah[0], ah[1], ah[2], ah[3], qHiA + ks*32);
                ldsm4(al[0], al[1], al[2], al[3], qLoA + ks*32);
#pragma unroll
                for (int p = 0; p < 4; p++) {
                    unsigned bh[4], bl[4];
                    ldsm4(bh[0], bh[1], bh[2], bh[3], kb   + kO[p] + ks*32);
                    ldsm4(bl[0], bl[1], bl[2], bl[3], kbLo + kO[p] + ks*32);
                    mma16(s[2*p],   ah, &bh[0]);
                    mma16(s[2*p],   ah, &bl[0]);
                    mma16(s[2*p],   al, &bh[0]);
                    mma16(s[2*p+1], ah, &bh[2]);
                    mma16(s[2*p+1], ah, &bl[2]);
                    mma16(s[2*p+1], al, &bh[2]);
                }
            }

            if (krow + 63 > qrow) {
                int q0 = qrow + g, q1 = q0 + 8;
#pragma unroll
                for (int nt = 0; nt < 8; nt++) {
                    int kc = krow + nt*8 + 2*t4;
                    if (kc     > q0) s[nt][0] = -1e30f;
                    if (kc + 1 > q0) s[nt][1] = -1e30f;
                    if (kc     > q1) s[nt][2] = -1e30f;
                    if (kc + 1 > q1) s[nt][3] = -1e30f;
                }
            }

            float mx0 = -1e30f, mx1 = -1e30f;
#pragma unroll
            for (int nt = 0; nt < 8; nt++) {
                mx0 = fmaxf(mx0, fmaxf(s[nt][0], s[nt][1]));
                mx1 = fmaxf(mx1, fmaxf(s[nt][2], s[nt][3]));
            }
            mx0 = fmaxf(mx0, __shfl_xor_sync(0xffffffffu, mx0, 1));
            mx0 = fmaxf(mx0, __shfl_xor_sync(0xffffffffu, mx0, 2));
            mx1 = fmaxf(mx1, __shfl_xor_sync(0xffffffffu, mx1, 1));
            mx1 = fmaxf(mx1, __shfl_xor_sync(0xffffffffu, mx1, 2));
            float mn0 = fmaxf(mst[0], mx0), mn1 = fmaxf(mst[1], mx1);
            float al0 = __expf(mst[0] - mn0), al1 = __expf(mst[1] - mn1);
            mst[0] = mn0; mst[1] = mn1;
            float rs0 = 0.f, rs1 = 0.f;
#pragma unroll
            for (int nt = 0; nt < 8; nt++) {
                s[nt][0] = __expf(s[nt][0] - mn0); rs0 += s[nt][0];
                s[nt][1] = __expf(s[nt][1] - mn0); rs0 += s[nt][1];
                s[nt][2] = __expf(s[nt][2] - mn1); rs1 += s[nt][2];
                s[nt][3] = __expf(s[nt][3] - mn1); rs1 += s[nt][3];
            }
            rs0 += __shfl_xor_sync(0xffffffffu, rs0, 1);
            rs0 += __shfl_xor_sync(0xffffffffu, rs0, 2);
            rs1 += __shfl_xor_sync(0xffffffffu, rs1, 1);
            rs1 += __shfl_xor_sync(0xffffffffu, rs1, 2);
            lst[0] = lst[0]*al0 + rs0;
            lst[1] = lst[1]*al1 + rs1;
#pragma unroll
            for (int dt = 0; dt < 8; dt++) {
                o[dt][0] *= al0; o[dt][1] *= al0;
                o[dt][2] *= al1; o[dt][3] *= al1;
            }

#pragma unroll
            for (int ks = 0; ks < 4; ks++) {
                unsigned pa[4];
                __half2 hp;
                hp = __floats2half2_rn(s[2*ks][0],   s[2*ks][1]);   pa[0] = *(unsigned*)&hp;
                hp = __floats2half2_rn(s[2*ks][2],   s[2*ks][3]);   pa[1] = *(unsigned*)&hp;
                hp = __floats2half2_rn(s[2*ks+1][0], s[2*ks+1][1]); pa[2] = *(unsigned*)&hp;
                hp = __floats2half2_rn(s[2*ks+1][2], s[2*ks+1][3]); pa[3] = *(unsigned*)&hp;
#pragma unroll
                for (int p = 0; p < 4; p++) {
                    unsigned vv[4];
                    ldsm4t(vv[0], vv[1], vv[2], vv[3], vb0 + vO[p] + ks*2304);
                    mmah(o[2*p],   pa, &vv[0]);
                    mmah(o[2*p+1], pa, &vv[2]);
                }
            }
        }
        st ^= 1;
    }

#pragma unroll
    for (int rr = 0; rr < 2; rr++) {
        int t = qrow + g + rr*8;
        float inv = 1.f / lst[rr];
        float ov[8][2];
        float pd = 0.f, pn = 0.f;
#pragma unroll
        for (int dt = 0; dt < 8; dt++) {
            float2 vv = *(const float2*)(vbase + (size_t)t*CHD + dt*8 + 2*t4);
            float o0 = o[dt][rr*2 + 0]*inv, o1 = o[dt][rr*2 + 1]*inv;
            ov[dt][0] = o0; ov[dt][1] = o1;
            pd += o0*vv.x + o1*vv.y;
            pn += vv.x*vv.x + vv.y*vv.y;
        }
        pd += __shfl_xor_sync(0xffffffffu, pd, 1);
        pd += __shfl_xor_sync(0xffffffffu, pd, 2);
        pn += __shfl_xor_sync(0xffffffffu, pn, 1);
        pn += __shfl_xor_sync(0xffffffffu, pn, 2);
        float coef = pd / fmaxf(pn, 1e-8f);
        size_t rowbase = ((size_t)b*CT + t)*CD2 + h*32;
#pragma unroll
        for (int dt = 0; dt < 8; dt++) {
            float2 vv = *(const float2*)(vbase + (size_t)t*CHD + dt*8 + 2*t4);
            unsigned hi, lo;
            split2(ov[dt][0] - coef*vv.x, ov[dt][1] - coef*vv.y, hi, lo);
            int d2 = dt*4 + t4;
            g_aohi[rowbase + d2] = hi;
            g_aolo[rowbase + d2] = lo;
        }
    }
}

// =================================================================
extern "C" void kernel_launch(void* const* d_in, const int* in_sizes, int n_in,
                              void* d_out, int out_size) {
    (void)in_sizes; (void)n_in; (void)out_size;
    const float* x    = (const float*)d_in[0];
    const float* cs   = (const float*)d_in[1];
    const float* sn   = (const float*)d_in[2];
    const float* wqkv = (const float*)d_in[4];
    const float* wout = (const float*)d_in[5];
    const float* qsc  = (const float*)d_in[6];
    const float* ksc  = (const float*)d_in[7];
    float* out = (float*)d_out;

    split_rows<<<CM + CNQKV + CD, 256>>>(x, wqkv, wout);

    const int qkv_smem = 2 * 40960;      // 81920 B
    cudaFuncSetAttribute(gemm_qkv, cudaFuncAttributeMaxDynamicSharedMemorySize, qkv_smem);
    dim3 g1(CNQKV/128, CM/128);          // 12 x 32
    gemm_qkv<<<g1, 256, qkv_smem>>>(qsc, ksc, cs, sn);

    const int attn_smem = (9216 + 2*6912) * 4;   // 92160 B
    cudaFuncSetAttribute(attn_pl, cudaFuncAttributeMaxDynamicSharedMemorySize, attn_smem);
    dim3 g2(CT/128, CNH, CB);            // 16 x 16 x 2
    attn_pl<<<g2, 256, attn_smem>>>();

    const int out_smem = 2 * 110592;     // 221184 B (2 stages, wide tile)
    cudaFuncSetAttribute(gemm_out, cudaFuncAttributeMaxDynamicSharedMemorySize, out_smem);
    dim3 g3(CD/256, CM/128);             // 4 x 32 = 128 CTAs, one wave
    gemm_out<<<g3, 512, out_smem>>>(out);
}